// round 14
// baseline (speedup 1.0000x reference)
#include <cuda_runtime.h>
#include <cuda_bf16.h>
#include <mma.h>
#include <math.h>
#include <stdint.h>

using namespace nvcuda;

// ---------------- problem constants ----------------
#define BB   16
#define CC   192
#define LL   4096              // H*W
#define MM   (BB*LL)           // 65536 rows
#define DI   384               // D_INNER
#define DS   16                // D_STATE
#define DTR  12                // DT_RANK
#define NX   44                // DTR + 2*DS (W_x col count)
#define NXP  64                // padded row stride of g_xdbc
#define NC   32                // scan chunks
#define CL   (LL/NC)           // 128 per chunk

// ---------------- scratch ----------------
__device__ __nv_bfloat16 g_xn [ (size_t)MM * CC ];   // LN out (GEMM1 A)
__device__ __nv_bfloat16 g_xi [ (size_t)MM * DI ];   // xi half of GEMM1 out
__device__ __nv_bfloat16 g_z  [ (size_t)MM * DI ];   // z  half of GEMM1 out
__device__ __nv_bfloat16 g_ub [ (size_t)MM * DI ];   // u = silu(conv(xi))
__device__ __nv_bfloat16 g_dt [ (size_t)MM * DI ];
__device__ float         g_xdbc[ (size_t)MM * NXP ]; // dt_r | B | C | pad (fp32)
__device__ __nv_bfloat16 g_yg [ (size_t)MM * DI ];   // gated y (GEMM3 A)
__device__ float g_P  [ (size_t)NC * BB * DI * DS ];
__device__ float g_hl [ (size_t)NC * BB * DI * DS ];
__device__ float g_hin[ (size_t)NC * BB * DI * DS ];

// ---------------- cp.async helper ----------------
__device__ __forceinline__ void cp16(void* s, const void* g) {
    uint32_t sa = (uint32_t)__cvta_generic_to_shared(s);
    asm volatile("cp.async.cg.shared.global [%0], [%1], 16;\n" :: "r"(sa), "l"(g));
}

// ---------------- K1: layernorm over C + layout to (B,L,C) bf16 -----------
__global__ void k_ln(const float* __restrict__ x, const float* __restrict__ g,
                     const float* __restrict__ bt) {
    __shared__ float s[CC][33];
    __shared__ float s_mu[32], s_rs[32];
    int b  = blockIdx.y;
    int p0 = blockIdx.x * 32;
    int tx = threadIdx.x, ty = threadIdx.y;
    const float* xb = x + (size_t)b * CC * LL;
    for (int c = ty; c < CC; c += 8)
        s[c][tx] = xb[(size_t)c * LL + p0 + tx];
    __syncthreads();
    int tid = ty * 32 + tx;
    if (tid < 32) {
        float sum = 0.f, sq = 0.f;
        #pragma unroll 4
        for (int c = 0; c < CC; c++) { float v = s[c][tid]; sum += v; sq += v*v; }
        float mu  = sum * (1.f/CC);
        float var = sq  * (1.f/CC) - mu*mu;
        s_mu[tid] = mu;
        s_rs[tid] = rsqrtf(var + 1e-5f);
    }
    __syncthreads();
    __nv_bfloat16* xnb = g_xn + ((size_t)b * LL + p0) * CC;
    for (int idx = tid; idx < 32 * CC; idx += 256) {
        int p = idx / CC, c = idx % CC;
        float v = (s[c][p] - s_mu[p]) * s_rs[p] * g[c] + bt[c];
        xnb[(size_t)p * CC + c] = __float2bfloat16_rn(v);
    }
}

// ---------------- K2: bf16 wmma GEMM, cp.async A, staged epilogues --------
// C = A[M,KK](bf16) @ B[KK,ldb](fp32). KK%32==0, tile 128x64.
// NGUARD: B has ldb(<64) valid cols, zero-padded (single col block).
// EPI 0: split bf16 store -> Cb1 (gc<DI) / Cb2 (gc>=DI), row stride DI.
// EPI 1: fp32 store cols<NX to Cf with row stride NXP.
// EPI 2: transposed + residual: Cf[(b*CC+n)*LL+l] = acc + Xres[same].
template<int KK, bool NGUARD, int EPI>
__global__ void __launch_bounds__(256, 2)
k_bgemm16(const __nv_bfloat16* __restrict__ A, const float* __restrict__ Bm,
          int ldb, float* __restrict__ Cf,
          __nv_bfloat16* __restrict__ Cb1, __nv_bfloat16* __restrict__ Cb2,
          const float* __restrict__ Xres) {
    __shared__ __align__(16) char sm[34816];
    __nv_bfloat16 (*As)[128][40] = (__nv_bfloat16 (*)[128][40])(sm);       // 20480B
    __nv_bfloat16 (*Bs)[72]      = (__nv_bfloat16 (*)[72])(sm + 20480);    // 4608B
    float         (*Cs)[68]      = (float (*)[68])(sm);                    // 34816B (aliases)

    const int t    = threadIdx.x;
    const int bm   = blockIdx.y * 128, bn = blockIdx.x * 64;
    const int warp = t >> 5;
    const int wm   = warp >> 1, wn = warp & 1;       // 4x2 warps, 32x32 each

    wmma::fragment<wmma::accumulator, 16, 16, 16, float> acc[2][2];
    #pragma unroll
    for (int i = 0; i < 2; i++)
        #pragma unroll
        for (int j = 0; j < 2; j++)
            wmma::fill_fragment(acc[i][j], 0.0f);

    // issue A tile 0 (128x32 bf16 = 512 16B chunks, 2 per thread)
    #pragma unroll
    for (int r = 0; r < 2; r++) {
        int c = t + r*256, row = c >> 2, cc = (c & 3) << 3;
        cp16(&As[0][row][cc], A + (size_t)(bm + row) * KK + cc);
    }
    asm volatile("cp.async.commit_group;\n" ::: "memory");

    const int nk = KK / 32;
    #pragma unroll
    for (int i = 0; i < nk; i++) {
        int buf = i & 1;
        if (i + 1 < nk) {
            #pragma unroll
            for (int r = 0; r < 2; r++) {
                int c = t + r*256, row = c >> 2, cc = (c & 3) << 3;
                cp16(&As[buf^1][row][cc],
                     A + (size_t)(bm + row) * KK + (i+1)*32 + cc);
            }
            asm volatile("cp.async.commit_group;\n" ::: "memory");
        }
        if (!NGUARD) {  // B tile 32x64, fp32 -> bf16
            int row = t >> 4, c4 = (t & 15) << 2;
            #pragma unroll
            for (int r2 = 0; r2 < 2; r2++) {
                float4 v = *(const float4*)(Bm + (size_t)(i*32 + row + r2*16) * ldb + bn + c4);
                *(__nv_bfloat162*)&Bs[row + r2*16][c4]     = __floats2bfloat162_rn(v.x, v.y);
                *(__nv_bfloat162*)&Bs[row + r2*16][c4 + 2] = __floats2bfloat162_rn(v.z, v.w);
            }
        } else {
            #pragma unroll
            for (int r2 = 0; r2 < 8; r2++) {
                int idx = r2*256 + t, row = idx >> 6, col = idx & 63;
                float v = (col < ldb) ? Bm[(size_t)(i*32 + row) * ldb + col] : 0.f;
                Bs[row][col] = __float2bfloat16_rn(v);
            }
        }
        if (i + 1 < nk) asm volatile("cp.async.wait_group 1;\n" ::: "memory");
        else            asm volatile("cp.async.wait_group 0;\n" ::: "memory");
        __syncthreads();
        #pragma unroll
        for (int kk = 0; kk < 32; kk += 16) {
            wmma::fragment<wmma::matrix_a, 16, 16, 16, __nv_bfloat16, wmma::row_major> fa[2];
            wmma::fragment<wmma::matrix_b, 16, 16, 16, __nv_bfloat16, wmma::row_major> fb[2];
            #pragma unroll
            for (int ii = 0; ii < 2; ii++)
                wmma::load_matrix_sync(fa[ii], &As[buf][wm*32 + ii*16][kk], 40);
            #pragma unroll
            for (int j = 0; j < 2; j++)
                wmma::load_matrix_sync(fb[j], &Bs[kk][wn*32 + j*16], 72);
            #pragma unroll
            for (int ii = 0; ii < 2; ii++)
                #pragma unroll
                for (int j = 0; j < 2; j++)
                    wmma::mma_sync(acc[ii][j], fa[ii], fb[j], acc[ii][j]);
        }
        __syncthreads();
    }

    // ---- stage accumulators to smem (fp32), then typed writes ----
    #pragma unroll
    for (int i = 0; i < 2; i++)
        #pragma unroll
        for (int j = 0; j < 2; j++)
            wmma::store_matrix_sync(&Cs[wm*32 + i*16][wn*32 + j*16],
                                    acc[i][j], 68, wmma::mem_row_major);
    __syncthreads();

    if (EPI == 0) {         // split bf16: xi / z
        #pragma unroll 4
        for (int it = 0; it < 32; it++) {
            int idx = t + it*256, row = idx >> 6, c = idx & 63;
            float v = Cs[row][c];
            size_t m = bm + row;
            int gc = bn + c;
            if (gc < DI) Cb1[m*DI + gc]      = __float2bfloat16_rn(v);
            else         Cb2[m*DI + gc - DI] = __float2bfloat16_rn(v);
        }
    } else if (EPI == 1) {  // fp32, cols < NX, stride NXP
        #pragma unroll 4
        for (int it = 0; it < 32; it++) {
            int idx = t + it*256, row = idx >> 6, c = idx & 63;
            int gc = bn + c;
            if (gc < NX) Cf[(size_t)(bm + row) * NXP + gc] = Cs[row][c];
        }
    } else {                // transposed + residual
        int b  = bm >> 12;
        int l0 = bm & 4095;
        #pragma unroll 4
        for (int it = 0; it < 32; it++) {
            int n = 2*it + (t >> 7);
            int l = t & 127;
            size_t off = ((size_t)b * CC + bn + n) * LL + l0 + l;
            Cf[off] = Cs[l][n] + Xres[off];
        }
    }
}

// ---------------- K3: depthwise causal conv + bias + silu -> bf16 u ------
__global__ void k_conv(const float* __restrict__ cw, const float* __restrict__ cb) {
    int idx = blockIdx.x * blockDim.x + threadIdx.x;
    if (idx >= MM * DI) return;
    int d = idx % DI;
    int l = (idx / DI) % LL;
    int b = idx / (DI * LL);
    const __nv_bfloat16* xi = g_xi + ((size_t)b * LL) * DI + d;
    float acc = cb[d];
    #pragma unroll
    for (int j = 0; j < 4; j++) {
        int ll = l - 3 + j;
        if (ll >= 0)
            acc = fmaf(cw[d*4 + j], __bfloat162float(xi[(size_t)ll * DI]), acc);
    }
    float u = acc / (1.f + __expf(-acc));
    g_ub[idx] = __float2bfloat16_rn(u);
}

// ---------------- K4: dt = softplus(dt_r @ W_dt + b_dt) -> bf16 ----------
__global__ void __launch_bounds__(384)
k_dt(const float* __restrict__ Wdt, const float* __restrict__ bdt) {
    __shared__ float sdtr[64][DTR];
    int m0 = blockIdx.x * 64;
    int d  = threadIdx.x;
    for (int i = d; i < 64 * DTR; i += 384)
        sdtr[i / DTR][i % DTR] = g_xdbc[(size_t)(m0 + i / DTR) * NXP + (i % DTR)];
    float w[DTR];
    #pragma unroll
    for (int k = 0; k < DTR; k++) w[k] = Wdt[k*DI + d];
    float bd = bdt[d];
    __syncthreads();
    for (int r = 0; r < 64; r++) {
        float acc = bd;
        #pragma unroll
        for (int k = 0; k < DTR; k++) acc = fmaf(sdtr[r][k], w[k], acc);
        float dt = (acc > 20.f) ? acc : log1pf(__expf(acc));
        g_dt[(size_t)(m0 + r) * DI + d] = __float2bfloat16_rn(dt);
    }
}

// ---------------- K5a: scan pass1 — per-chunk P and local end state -------
__global__ void __launch_bounds__(128)
k_scan1(const float* __restrict__ Alog) {
    int gid = blockIdx.x * 128 + threadIdx.x;
    int grp = gid >> 4;
    int s   = gid & 15;
    int c   = grp / (BB * DI);
    int bd  = grp % (BB * DI);
    int b = bd / DI, d = bd % DI;
    float A = -__expf(Alog[d*DS + s]);
    size_t m0 = (size_t)b * LL + (size_t)c * CL;
    const __nv_bfloat16* up  = g_ub + m0 * DI + d;
    const __nv_bfloat16* dtp = g_dt + m0 * DI + d;
    const float*         Bp  = g_xdbc + m0 * NXP + DTR + s;
    float h = 0.f, P = 1.f;
    #pragma unroll 4
    for (int l = 0; l < CL; l++) {
        float ut  = __bfloat162float(up [(size_t)l * DI]);
        float dtt = __bfloat162float(dtp[(size_t)l * DI]);
        float Bv  = Bp[(size_t)l * NXP];
        float dA  = __expf(dtt * A);
        P *= dA;
        h = fmaf(h, dA, dtt * ut * Bv);
    }
    g_P [gid] = P;
    g_hl[gid] = h;
}

// ---------------- K5b: serial combine over chunks -------------------------
__global__ void k_scan2() {
    int bds = blockIdx.x * blockDim.x + threadIdx.x;
    if (bds >= BB * DI * DS) return;
    const int STRIDE = BB * DI * DS;
    float h = 0.f;
    #pragma unroll
    for (int c = 0; c < NC; c++) {
        g_hin[(size_t)c * STRIDE + bds] = h;
        h = fmaf(g_P[(size_t)c * STRIDE + bds], h, g_hl[(size_t)c * STRIDE + bds]);
    }
}

// ---------------- K5c: scan pass3 — scan from h_in, emit gated y (bf16) ---
__global__ void __launch_bounds__(128)
k_scan3(const float* __restrict__ Alog, const float* __restrict__ Dp) {
    int gid = blockIdx.x * 128 + threadIdx.x;
    int grp = gid >> 4;
    int s   = gid & 15;
    int c   = grp / (BB * DI);
    int bd  = grp % (BB * DI);
    int b = bd / DI, d = bd % DI;
    float A   = -__expf(Alog[d*DS + s]);
    float Dpd = Dp[d];
    size_t m0 = (size_t)b * LL + (size_t)c * CL;
    const __nv_bfloat16* up  = g_ub + m0 * DI + d;
    const __nv_bfloat16* dtp = g_dt + m0 * DI + d;
    const float*         Bp  = g_xdbc + m0 * NXP + DTR + s;
    const float*         Cp  = g_xdbc + m0 * NXP + DTR + DS + s;
    const __nv_bfloat16* zp  = g_z  + m0 * DI + d;
    __nv_bfloat16*       yp  = g_yg + m0 * DI + d;
    float h = g_hin[gid];
    #pragma unroll 2
    for (int l = 0; l < CL; l++) {
        float ut  = __bfloat162float(up [(size_t)l * DI]);
        float dtt = __bfloat162float(dtp[(size_t)l * DI]);
        float Bv  = Bp[(size_t)l * NXP];
        float Cv  = Cp[(size_t)l * NXP];
        float dA  = __expf(dtt * A);
        h = fmaf(h, dA, dtt * ut * Bv);
        float pr = h * Cv;
        pr += __shfl_xor_sync(0xffffffffu, pr, 8, 16);
        pr += __shfl_xor_sync(0xffffffffu, pr, 4, 16);
        pr += __shfl_xor_sync(0xffffffffu, pr, 2, 16);
        pr += __shfl_xor_sync(0xffffffffu, pr, 1, 16);
        if (s == 0) {
            float y = pr + ut * Dpd;
            float z = __bfloat162float(zp[(size_t)l * DI]);
            y *= z / (1.f + __expf(-z));
            yp[(size_t)l * DI] = __float2bfloat16_rn(y);
        }
    }
}

// ---------------- launch ----------------
extern "C" void kernel_launch(void* const* d_in, const int* in_sizes, int n_in,
                              void* d_out, int out_size) {
    const float* x      = (const float*)d_in[0];
    const float* ln_g   = (const float*)d_in[1];
    const float* ln_b   = (const float*)d_in[2];
    const float* W_in   = (const float*)d_in[3];
    const float* conv_w = (const float*)d_in[4];
    const float* conv_b = (const float*)d_in[5];
    const float* W_x    = (const float*)d_in[6];
    const float* W_dt   = (const float*)d_in[7];
    const float* b_dt   = (const float*)d_in[8];
    const float* A_log  = (const float*)d_in[9];
    const float* Dp     = (const float*)d_in[10];
    const float* W_out  = (const float*)d_in[11];
    float* out = (float*)d_out;

    __nv_bfloat16 *p_xn, *p_xi, *p_z, *p_ub, *p_yg;
    float *p_xdbc;
    cudaGetSymbolAddress((void**)&p_xn,   g_xn);
    cudaGetSymbolAddress((void**)&p_xi,   g_xi);
    cudaGetSymbolAddress((void**)&p_z,    g_z);
    cudaGetSymbolAddress((void**)&p_ub,   g_ub);
    cudaGetSymbolAddress((void**)&p_xdbc, g_xdbc);
    cudaGetSymbolAddress((void**)&p_yg,   g_yg);

    {   // layernorm -> bf16 (B,L,C)
        dim3 grid(LL/32, BB), blk(32, 8);
        k_ln<<<grid, blk>>>(x, ln_g, ln_b);
    }
    {   // GEMM1: [xi|z] = xn @ W_in, split bf16 epilogue
        dim3 grid((2*DI)/64, MM/128);
        k_bgemm16<CC, false, 0><<<grid, 256>>>(p_xn, W_in, 2*DI,
                                               nullptr, p_xi, p_z, nullptr);
    }
    {   // conv + silu -> ub (bf16)
        int n = MM * DI;
        k_conv<<<(n + 255)/256, 256>>>(conv_w, conv_b);
    }
    {   // xdbc = u @ W_x (44 valid cols, fp32 out stride 64)
        dim3 grid(1, MM/128);
        k_bgemm16<DI, true, 1><<<grid, 256>>>(p_ub, W_x, NX,
                                              p_xdbc, nullptr, nullptr, nullptr);
    }
    // dt (bf16)
    k_dt<<<MM/64, 384>>>(W_dt, b_dt);
    // chunked scan
    k_scan1<<<(NC*BB*DI*DS)/128, 128>>>(A_log);
    k_scan2<<<(BB*DI*DS + 255)/256, 256>>>();
    k_scan3<<<(NC*BB*DI*DS)/128, 128>>>(A_log, Dp);
    {   // GEMM3 fused transpose+residual: out = (yg @ W_out)^T + x
        dim3 grid(CC/64, MM/128);
        k_bgemm16<DI, false, 2><<<grid, 256>>>(p_yg, W_out, CC,
                                               out, nullptr, nullptr, x);
    }
}

// round 15
// speedup vs baseline: 1.2895x; 1.2895x over previous
#include <cuda_runtime.h>
#include <cuda_bf16.h>
#include <mma.h>
#include <math.h>
#include <stdint.h>

using namespace nvcuda;

// ---------------- problem constants ----------------
#define BB   16
#define CC   192
#define LL   4096              // H*W
#define MM   (BB*LL)           // 65536 rows
#define DI   384               // D_INNER
#define DS   16                // D_STATE
#define DTR  12                // DT_RANK
#define NX   44                // DTR + 2*DS (W_x col count)
#define NXP  64                // padded row stride of g_xdbc
#define NC   32                // scan chunks
#define CL   (LL/NC)           // 128 per chunk

// ---------------- scratch ----------------
__device__ __nv_bfloat16 g_xn [ (size_t)MM * CC ];   // LN out (GEMM1 A)
__device__ __nv_bfloat16 g_xi [ (size_t)MM * DI ];   // xi half of GEMM1 out
__device__ __nv_bfloat16 g_z  [ (size_t)MM * DI ];   // z  half of GEMM1 out
__device__ __nv_bfloat16 g_ub [ (size_t)MM * DI ];   // u = silu(conv(xi))
__device__ __nv_bfloat16 g_dt [ (size_t)MM * DI ];
__device__ float         g_xdbc[ (size_t)MM * NXP ]; // dt_r | B | C | pad (fp32)
__device__ __nv_bfloat16 g_yg [ (size_t)MM * DI ];   // gated y (GEMM3 A)
__device__ float g_P  [ (size_t)NC * BB * DI * DS ];
__device__ float g_hl [ (size_t)NC * BB * DI * DS ];
__device__ float g_hin[ (size_t)NC * BB * DI * DS ];

// ---------------- cp.async helper ----------------
__device__ __forceinline__ void cp16(void* s, const void* g) {
    uint32_t sa = (uint32_t)__cvta_generic_to_shared(s);
    asm volatile("cp.async.cg.shared.global [%0], [%1], 16;\n" :: "r"(sa), "l"(g));
}

// ---------------- K1: layernorm over C + layout to (B,L,C) bf16 -----------
__global__ void k_ln(const float* __restrict__ x, const float* __restrict__ g,
                     const float* __restrict__ bt) {
    __shared__ float s[CC][33];
    __shared__ float s_mu[32], s_rs[32];
    int b  = blockIdx.y;
    int p0 = blockIdx.x * 32;
    int tx = threadIdx.x, ty = threadIdx.y;
    const float* xb = x + (size_t)b * CC * LL;
    for (int c = ty; c < CC; c += 8)
        s[c][tx] = xb[(size_t)c * LL + p0 + tx];
    __syncthreads();
    int tid = ty * 32 + tx;
    if (tid < 32) {
        float sum = 0.f, sq = 0.f;
        #pragma unroll 4
        for (int c = 0; c < CC; c++) { float v = s[c][tid]; sum += v; sq += v*v; }
        float mu  = sum * (1.f/CC);
        float var = sq  * (1.f/CC) - mu*mu;
        s_mu[tid] = mu;
        s_rs[tid] = rsqrtf(var + 1e-5f);
    }
    __syncthreads();
    __nv_bfloat16* xnb = g_xn + ((size_t)b * LL + p0) * CC;
    for (int idx = tid; idx < 32 * CC; idx += 256) {
        int p = idx / CC, c = idx % CC;
        float v = (s[c][p] - s_mu[p]) * s_rs[p] * g[c] + bt[c];
        xnb[(size_t)p * CC + c] = __float2bfloat16_rn(v);
    }
}

// ---------------- K2: bf16 wmma GEMM, cp.async A, staged epilogues --------
// C = A[M,KK](bf16) @ B[KK,ldb](fp32). KK%32==0, tile 128x64.
// NGUARD: B has ldb(<64) valid cols, zero-padded (single col block).
// EPI 0: split bf16 store -> Cb1 (gc<DI) / Cb2 (gc>=DI), row stride DI.
// EPI 1: fp32 store cols<NX to Cf with row stride NXP.
// EPI 2: transposed + residual: Cf[(b*CC+n)*LL+l] = acc + Xres[same].
template<int KK, bool NGUARD, int EPI>
__global__ void __launch_bounds__(256)
k_bgemm16(const __nv_bfloat16* __restrict__ A, const float* __restrict__ Bm,
          int ldb, float* __restrict__ Cf,
          __nv_bfloat16* __restrict__ Cb1, __nv_bfloat16* __restrict__ Cb2,
          const float* __restrict__ Xres) {
    __shared__ __align__(16) char sm[34816];
    __nv_bfloat16 (*As)[128][40] = (__nv_bfloat16 (*)[128][40])(sm);       // 20480B
    __nv_bfloat16 (*Bs)[72]      = (__nv_bfloat16 (*)[72])(sm + 20480);    // 4608B
    float         (*Cs)[68]      = (float (*)[68])(sm);                    // 34816B (aliases)

    const int t    = threadIdx.x;
    const int bm   = blockIdx.y * 128, bn = blockIdx.x * 64;
    const int warp = t >> 5;
    const int wm   = warp >> 1, wn = warp & 1;       // 4x2 warps, 32x32 each

    wmma::fragment<wmma::accumulator, 16, 16, 16, float> acc[2][2];
    #pragma unroll
    for (int i = 0; i < 2; i++)
        #pragma unroll
        for (int j = 0; j < 2; j++)
            wmma::fill_fragment(acc[i][j], 0.0f);

    // issue A tile 0 (128x32 bf16 = 512 16B chunks, 2 per thread)
    #pragma unroll
    for (int r = 0; r < 2; r++) {
        int c = t + r*256, row = c >> 2, cc = (c & 3) << 3;
        cp16(&As[0][row][cc], A + (size_t)(bm + row) * KK + cc);
    }
    asm volatile("cp.async.commit_group;\n" ::: "memory");

    const int nk = KK / 32;
    #pragma unroll
    for (int i = 0; i < nk; i++) {
        int buf = i & 1;
        if (i + 1 < nk) {
            #pragma unroll
            for (int r = 0; r < 2; r++) {
                int c = t + r*256, row = c >> 2, cc = (c & 3) << 3;
                cp16(&As[buf^1][row][cc],
                     A + (size_t)(bm + row) * KK + (i+1)*32 + cc);
            }
            asm volatile("cp.async.commit_group;\n" ::: "memory");
        }
        if (!NGUARD) {  // B tile 32x64, fp32 -> bf16
            int row = t >> 4, c4 = (t & 15) << 2;
            #pragma unroll
            for (int r2 = 0; r2 < 2; r2++) {
                float4 v = *(const float4*)(Bm + (size_t)(i*32 + row + r2*16) * ldb + bn + c4);
                *(__nv_bfloat162*)&Bs[row + r2*16][c4]     = __floats2bfloat162_rn(v.x, v.y);
                *(__nv_bfloat162*)&Bs[row + r2*16][c4 + 2] = __floats2bfloat162_rn(v.z, v.w);
            }
        } else {
            #pragma unroll
            for (int r2 = 0; r2 < 8; r2++) {
                int idx = r2*256 + t, row = idx >> 6, col = idx & 63;
                float v = (col < ldb) ? Bm[(size_t)(i*32 + row) * ldb + col] : 0.f;
                Bs[row][col] = __float2bfloat16_rn(v);
            }
        }
        if (i + 1 < nk) asm volatile("cp.async.wait_group 1;\n" ::: "memory");
        else            asm volatile("cp.async.wait_group 0;\n" ::: "memory");
        __syncthreads();
        #pragma unroll
        for (int kk = 0; kk < 32; kk += 16) {
            wmma::fragment<wmma::matrix_a, 16, 16, 16, __nv_bfloat16, wmma::row_major> fa[2];
            wmma::fragment<wmma::matrix_b, 16, 16, 16, __nv_bfloat16, wmma::row_major> fb[2];
            #pragma unroll
            for (int ii = 0; ii < 2; ii++)
                wmma::load_matrix_sync(fa[ii], &As[buf][wm*32 + ii*16][kk], 40);
            #pragma unroll
            for (int j = 0; j < 2; j++)
                wmma::load_matrix_sync(fb[j], &Bs[kk][wn*32 + j*16], 72);
            #pragma unroll
            for (int ii = 0; ii < 2; ii++)
                #pragma unroll
                for (int j = 0; j < 2; j++)
                    wmma::mma_sync(acc[ii][j], fa[ii], fb[j], acc[ii][j]);
        }
        __syncthreads();
    }

    // ---- stage accumulators to smem (fp32), then typed writes ----
    #pragma unroll
    for (int i = 0; i < 2; i++)
        #pragma unroll
        for (int j = 0; j < 2; j++)
            wmma::store_matrix_sync(&Cs[wm*32 + i*16][wn*32 + j*16],
                                    acc[i][j], 68, wmma::mem_row_major);
    __syncthreads();

    if (EPI == 0) {         // split bf16: xi / z
        #pragma unroll 4
        for (int it = 0; it < 32; it++) {
            int idx = t + it*256, row = idx >> 6, c = idx & 63;
            float v = Cs[row][c];
            size_t m = bm + row;
            int gc = bn + c;
            if (gc < DI) Cb1[m*DI + gc]      = __float2bfloat16_rn(v);
            else         Cb2[m*DI + gc - DI] = __float2bfloat16_rn(v);
        }
    } else if (EPI == 1) {  // fp32, cols < NX, stride NXP
        #pragma unroll 4
        for (int it = 0; it < 32; it++) {
            int idx = t + it*256, row = idx >> 6, c = idx & 63;
            int gc = bn + c;
            if (gc < NX) Cf[(size_t)(bm + row) * NXP + gc] = Cs[row][c];
        }
    } else {                // transposed + residual
        int b  = bm >> 12;
        int l0 = bm & 4095;
        #pragma unroll 4
        for (int it = 0; it < 32; it++) {
            int n = 2*it + (t >> 7);
            int l = t & 127;
            size_t off = ((size_t)b * CC + bn + n) * LL + l0 + l;
            Cf[off] = Cs[l][n] + Xres[off];
        }
    }
}

// ---------------- K3: depthwise causal conv + bias + silu -> bf16 u ------
__global__ void k_conv(const float* __restrict__ cw, const float* __restrict__ cb) {
    int idx = blockIdx.x * blockDim.x + threadIdx.x;
    if (idx >= MM * DI) return;
    int d = idx % DI;
    int l = (idx / DI) % LL;
    int b = idx / (DI * LL);
    const __nv_bfloat16* xi = g_xi + ((size_t)b * LL) * DI + d;
    float acc = cb[d];
    #pragma unroll
    for (int j = 0; j < 4; j++) {
        int ll = l - 3 + j;
        if (ll >= 0)
            acc = fmaf(cw[d*4 + j], __bfloat162float(xi[(size_t)ll * DI]), acc);
    }
    float u = acc / (1.f + __expf(-acc));
    g_ub[idx] = __float2bfloat16_rn(u);
}

// ---------------- K4: dt = softplus(dt_r @ W_dt + b_dt) -> bf16 ----------
__global__ void __launch_bounds__(384)
k_dt(const float* __restrict__ Wdt, const float* __restrict__ bdt) {
    __shared__ float sdtr[64][DTR];
    int m0 = blockIdx.x * 64;
    int d  = threadIdx.x;
    for (int i = d; i < 64 * DTR; i += 384)
        sdtr[i / DTR][i % DTR] = g_xdbc[(size_t)(m0 + i / DTR) * NXP + (i % DTR)];
    float w[DTR];
    #pragma unroll
    for (int k = 0; k < DTR; k++) w[k] = Wdt[k*DI + d];
    float bd = bdt[d];
    __syncthreads();
    for (int r = 0; r < 64; r++) {
        float acc = bd;
        #pragma unroll
        for (int k = 0; k < DTR; k++) acc = fmaf(sdtr[r][k], w[k], acc);
        float dt = (acc > 20.f) ? acc : log1pf(__expf(acc));
        g_dt[(size_t)(m0 + r) * DI + d] = __float2bfloat16_rn(dt);
    }
}

// ---------------- K5a: scan pass1 — per-chunk P and local end state -------
__global__ void __launch_bounds__(128)
k_scan1(const float* __restrict__ Alog) {
    int gid = blockIdx.x * 128 + threadIdx.x;
    int grp = gid >> 4;
    int s   = gid & 15;
    int c   = grp / (BB * DI);
    int bd  = grp % (BB * DI);
    int b = bd / DI, d = bd % DI;
    float A = -__expf(Alog[d*DS + s]);
    size_t m0 = (size_t)b * LL + (size_t)c * CL;
    const __nv_bfloat16* up  = g_ub + m0 * DI + d;
    const __nv_bfloat16* dtp = g_dt + m0 * DI + d;
    const float*         Bp  = g_xdbc + m0 * NXP + DTR + s;
    float h = 0.f, P = 1.f;
    #pragma unroll 4
    for (int l = 0; l < CL; l++) {
        float ut  = __bfloat162float(up [(size_t)l * DI]);
        float dtt = __bfloat162float(dtp[(size_t)l * DI]);
        float Bv  = Bp[(size_t)l * NXP];
        float dA  = __expf(dtt * A);
        P *= dA;
        h = fmaf(h, dA, dtt * ut * Bv);
    }
    g_P [gid] = P;
    g_hl[gid] = h;
}

// ---------------- K5b: serial combine over chunks -------------------------
__global__ void k_scan2() {
    int bds = blockIdx.x * blockDim.x + threadIdx.x;
    if (bds >= BB * DI * DS) return;
    const int STRIDE = BB * DI * DS;
    float h = 0.f;
    #pragma unroll
    for (int c = 0; c < NC; c++) {
        g_hin[(size_t)c * STRIDE + bds] = h;
        h = fmaf(g_P[(size_t)c * STRIDE + bds], h, g_hl[(size_t)c * STRIDE + bds]);
    }
}

// ---------------- K5c: scan pass3 — scan from h_in, emit gated y (bf16) ---
__global__ void __launch_bounds__(128)
k_scan3(const float* __restrict__ Alog, const float* __restrict__ Dp) {
    int gid = blockIdx.x * 128 + threadIdx.x;
    int grp = gid >> 4;
    int s   = gid & 15;
    int c   = grp / (BB * DI);
    int bd  = grp % (BB * DI);
    int b = bd / DI, d = bd % DI;
    float A   = -__expf(Alog[d*DS + s]);
    float Dpd = Dp[d];
    size_t m0 = (size_t)b * LL + (size_t)c * CL;
    const __nv_bfloat16* up  = g_ub + m0 * DI + d;
    const __nv_bfloat16* dtp = g_dt + m0 * DI + d;
    const float*         Bp  = g_xdbc + m0 * NXP + DTR + s;
    const float*         Cp  = g_xdbc + m0 * NXP + DTR + DS + s;
    const __nv_bfloat16* zp  = g_z  + m0 * DI + d;
    __nv_bfloat16*       yp  = g_yg + m0 * DI + d;
    float h = g_hin[gid];
    #pragma unroll 2
    for (int l = 0; l < CL; l++) {
        float ut  = __bfloat162float(up [(size_t)l * DI]);
        float dtt = __bfloat162float(dtp[(size_t)l * DI]);
        float Bv  = Bp[(size_t)l * NXP];
        float Cv  = Cp[(size_t)l * NXP];
        float dA  = __expf(dtt * A);
        h = fmaf(h, dA, dtt * ut * Bv);
        float pr = h * Cv;
        pr += __shfl_xor_sync(0xffffffffu, pr, 8, 16);
        pr += __shfl_xor_sync(0xffffffffu, pr, 4, 16);
        pr += __shfl_xor_sync(0xffffffffu, pr, 2, 16);
        pr += __shfl_xor_sync(0xffffffffu, pr, 1, 16);
        if (s == 0) {
            float y = pr + ut * Dpd;
            float z = __bfloat162float(zp[(size_t)l * DI]);
            y *= z / (1.f + __expf(-z));
            yp[(size_t)l * DI] = __float2bfloat16_rn(y);
        }
    }
}

// ---------------- launch ----------------
extern "C" void kernel_launch(void* const* d_in, const int* in_sizes, int n_in,
                              void* d_out, int out_size) {
    const float* x      = (const float*)d_in[0];
    const float* ln_g   = (const float*)d_in[1];
    const float* ln_b   = (const float*)d_in[2];
    const float* W_in   = (const float*)d_in[3];
    const float* conv_w = (const float*)d_in[4];
    const float* conv_b = (const float*)d_in[5];
    const float* W_x    = (const float*)d_in[6];
    const float* W_dt   = (const float*)d_in[7];
    const float* b_dt   = (const float*)d_in[8];
    const float* A_log  = (const float*)d_in[9];
    const float* Dp     = (const float*)d_in[10];
    const float* W_out  = (const float*)d_in[11];
    float* out = (float*)d_out;

    __nv_bfloat16 *p_xn, *p_xi, *p_z, *p_ub, *p_yg;
    float *p_xdbc;
    cudaGetSymbolAddress((void**)&p_xn,   g_xn);
    cudaGetSymbolAddress((void**)&p_xi,   g_xi);
    cudaGetSymbolAddress((void**)&p_z,    g_z);
    cudaGetSymbolAddress((void**)&p_ub,   g_ub);
    cudaGetSymbolAddress((void**)&p_xdbc, g_xdbc);
    cudaGetSymbolAddress((void**)&p_yg,   g_yg);

    {   // layernorm -> bf16 (B,L,C)
        dim3 grid(LL/32, BB), blk(32, 8);
        k_ln<<<grid, blk>>>(x, ln_g, ln_b);
    }
    {   // GEMM1: [xi|z] = xn @ W_in, split bf16 epilogue
        dim3 grid((2*DI)/64, MM/128);
        k_bgemm16<CC, false, 0><<<grid, 256>>>(p_xn, W_in, 2*DI,
                                               nullptr, p_xi, p_z, nullptr);
    }
    {   // conv + silu -> ub (bf16)
        int n = MM * DI;
        k_conv<<<(n + 255)/256, 256>>>(conv_w, conv_b);
    }
    {   // xdbc = u @ W_x (44 valid cols, fp32 out stride 64)
        dim3 grid(1, MM/128);
        k_bgemm16<DI, true, 1><<<grid, 256>>>(p_ub, W_x, NX,
                                              p_xdbc, nullptr, nullptr, nullptr);
    }
    // dt (bf16)
    k_dt<<<MM/64, 384>>>(W_dt, b_dt);
    // chunked scan
    k_scan1<<<(NC*BB*DI*DS)/128, 128>>>(A_log);
    k_scan2<<<(BB*DI*DS + 255)/256, 256>>>();
    k_scan3<<<(NC*BB*DI*DS)/128, 128>>>(A_log, Dp);
    {   // GEMM3 fused transpose+residual: out = (yg @ W_out)^T + x
        dim3 grid(CC/64, MM/128);
        k_bgemm16<DI, false, 2><<<grid, 256>>>(p_yg, W_out, CC,
                                               out, nullptr, nullptr, x);
    }
}

// round 17
// speedup vs baseline: 3.6861x; 2.8585x over previous
#include <cuda_runtime.h>
#include <cuda_bf16.h>
#include <mma.h>
#include <math.h>
#include <stdint.h>

using namespace nvcuda;

// ---------------- problem constants ----------------
#define BB   16
#define CC   192
#define LL   4096              // H*W
#define MM   (BB*LL)           // 65536 rows
#define DI   384               // D_INNER
#define DS   16                // D_STATE
#define DTR  12                // DT_RANK
#define NX   44                // DTR + 2*DS (W_x col count)
#define NXP  64                // padded row stride of g_xdbc
#define NC   32                // scan chunks
#define CL   (LL/NC)           // 128 per chunk

// ---------------- scratch ----------------
__device__ __nv_bfloat16 g_xn [ (size_t)MM * CC ];   // LN out (GEMM1 A)
__device__ __nv_bfloat16 g_xi [ (size_t)MM * DI ];   // xi half of GEMM1 out
__device__ __nv_bfloat16 g_z  [ (size_t)MM * DI ];   // z  half of GEMM1 out
__device__ __nv_bfloat16 g_ub [ (size_t)MM * DI ];   // u = silu(conv(xi))
__device__ __nv_bfloat16 g_dt [ (size_t)MM * DI ];
__device__ float         g_xdbc[ (size_t)MM * NXP ]; // dt_r | B | C | pad (fp32)
__device__ __nv_bfloat16 g_yg [ (size_t)MM * DI ];   // gated y (GEMM3 A)
__device__ float g_P  [ (size_t)NC * BB * DI * DS ];
__device__ float g_hl [ (size_t)NC * BB * DI * DS ];
__device__ float g_hin[ (size_t)NC * BB * DI * DS ];

// ---------------- helpers ----------------
__device__ __forceinline__ void cp16(void* s, const void* g) {
    uint32_t sa = (uint32_t)__cvta_generic_to_shared(s);
    asm volatile("cp.async.cg.shared.global [%0], [%1], 16;\n" :: "r"(sa), "l"(g));
}
// packed f32x2 (sm_103a)
__device__ __forceinline__ uint64_t pk(float lo, float hi) {
    uint64_t r; asm("mov.b64 %0, {%1, %2};" : "=l"(r) : "f"(lo), "f"(hi)); return r;
}
__device__ __forceinline__ void upk(uint64_t v, float& lo, float& hi) {
    asm("mov.b64 {%0, %1}, %2;" : "=f"(lo), "=f"(hi) : "l"(v));
}
__device__ __forceinline__ uint64_t fma2(uint64_t a, uint64_t b, uint64_t c) {
    uint64_t d; asm("fma.rn.f32x2 %0, %1, %2, %3;" : "=l"(d) : "l"(a), "l"(b), "l"(c)); return d;
}
__device__ __forceinline__ uint64_t mul2(uint64_t a, uint64_t b) {
    uint64_t d; asm("mul.rn.f32x2 %0, %1, %2;" : "=l"(d) : "l"(a), "l"(b)); return d;
}

// ---------------- K1: layernorm over C + layout to (B,L,C) bf16 -----------
__global__ void k_ln(const float* __restrict__ x, const float* __restrict__ g,
                     const float* __restrict__ bt) {
    __shared__ float s[CC][33];
    __shared__ float s_mu[32], s_rs[32];
    int b  = blockIdx.y;
    int p0 = blockIdx.x * 32;
    int tx = threadIdx.x, ty = threadIdx.y;
    const float* xb = x + (size_t)b * CC * LL;
    for (int c = ty; c < CC; c += 8)
        s[c][tx] = xb[(size_t)c * LL + p0 + tx];
    __syncthreads();
    int tid = ty * 32 + tx;
    if (tid < 32) {
        float sum = 0.f, sq = 0.f;
        #pragma unroll 4
        for (int c = 0; c < CC; c++) { float v = s[c][tid]; sum += v; sq += v*v; }
        float mu  = sum * (1.f/CC);
        float var = sq  * (1.f/CC) - mu*mu;
        s_mu[tid] = mu;
        s_rs[tid] = rsqrtf(var + 1e-5f);
    }
    __syncthreads();
    __nv_bfloat16* xnb = g_xn + ((size_t)b * LL + p0) * CC;
    for (int idx = tid; idx < 32 * CC; idx += 256) {
        int p = idx / CC, c = idx % CC;
        float v = (s[c][p] - s_mu[p]) * s_rs[p] * g[c] + bt[c];
        xnb[(size_t)p * CC + c] = __float2bfloat16_rn(v);
    }
}

// ---------------- K2: bf16 wmma GEMM, cp.async A, staged epilogues --------
template<int KK, bool NGUARD, int EPI>
__global__ void __launch_bounds__(256)
k_bgemm16(const __nv_bfloat16* __restrict__ A, const float* __restrict__ Bm,
          int ldb, float* __restrict__ Cf,
          __nv_bfloat16* __restrict__ Cb1, __nv_bfloat16* __restrict__ Cb2,
          const float* __restrict__ Xres) {
    __shared__ __align__(16) char sm[34816];
    __nv_bfloat16 (*As)[128][40] = (__nv_bfloat16 (*)[128][40])(sm);
    __nv_bfloat16 (*Bs)[72]      = (__nv_bfloat16 (*)[72])(sm + 20480);
    float         (*Cs)[68]      = (float (*)[68])(sm);

    const int t    = threadIdx.x;
    const int bm   = blockIdx.y * 128, bn = blockIdx.x * 64;
    const int warp = t >> 5;
    const int wm   = warp >> 1, wn = warp & 1;

    wmma::fragment<wmma::accumulator, 16, 16, 16, float> acc[2][2];
    #pragma unroll
    for (int i = 0; i < 2; i++)
        #pragma unroll
        for (int j = 0; j < 2; j++)
            wmma::fill_fragment(acc[i][j], 0.0f);

    #pragma unroll
    for (int r = 0; r < 2; r++) {
        int c = t + r*256, row = c >> 2, cc = (c & 3) << 3;
        cp16(&As[0][row][cc], A + (size_t)(bm + row) * KK + cc);
    }
    asm volatile("cp.async.commit_group;\n" ::: "memory");

    const int nk = KK / 32;
    #pragma unroll
    for (int i = 0; i < nk; i++) {
        int buf = i & 1;
        if (i + 1 < nk) {
            #pragma unroll
            for (int r = 0; r < 2; r++) {
                int c = t + r*256, row = c >> 2, cc = (c & 3) << 3;
                cp16(&As[buf^1][row][cc],
                     A + (size_t)(bm + row) * KK + (i+1)*32 + cc);
            }
            asm volatile("cp.async.commit_group;\n" ::: "memory");
        }
        if (!NGUARD) {
            int row = t >> 4, c4 = (t & 15) << 2;
            #pragma unroll
            for (int r2 = 0; r2 < 2; r2++) {
                float4 v = *(const float4*)(Bm + (size_t)(i*32 + row + r2*16) * ldb + bn + c4);
                *(__nv_bfloat162*)&Bs[row + r2*16][c4]     = __floats2bfloat162_rn(v.x, v.y);
                *(__nv_bfloat162*)&Bs[row + r2*16][c4 + 2] = __floats2bfloat162_rn(v.z, v.w);
            }
        } else {
            #pragma unroll
            for (int r2 = 0; r2 < 8; r2++) {
                int idx = r2*256 + t, row = idx >> 6, col = idx & 63;
                float v = (col < ldb) ? Bm[(size_t)(i*32 + row) * ldb + col] : 0.f;
                Bs[row][col] = __float2bfloat16_rn(v);
            }
        }
        if (i + 1 < nk) asm volatile("cp.async.wait_group 1;\n" ::: "memory");
        else            asm volatile("cp.async.wait_group 0;\n" ::: "memory");
        __syncthreads();
        #pragma unroll
        for (int kk = 0; kk < 32; kk += 16) {
            wmma::fragment<wmma::matrix_a, 16, 16, 16, __nv_bfloat16, wmma::row_major> fa[2];
            wmma::fragment<wmma::matrix_b, 16, 16, 16, __nv_bfloat16, wmma::row_major> fb[2];
            #pragma unroll
            for (int ii = 0; ii < 2; ii++)
                wmma::load_matrix_sync(fa[ii], &As[buf][wm*32 + ii*16][kk], 40);
            #pragma unroll
            for (int j = 0; j < 2; j++)
                wmma::load_matrix_sync(fb[j], &Bs[kk][wn*32 + j*16], 72);
            #pragma unroll
            for (int ii = 0; ii < 2; ii++)
                #pragma unroll
                for (int j = 0; j < 2; j++)
                    wmma::mma_sync(acc[ii][j], fa[ii], fb[j], acc[ii][j]);
        }
        __syncthreads();
    }

    #pragma unroll
    for (int i = 0; i < 2; i++)
        #pragma unroll
        for (int j = 0; j < 2; j++)
            wmma::store_matrix_sync(&Cs[wm*32 + i*16][wn*32 + j*16],
                                    acc[i][j], 68, wmma::mem_row_major);
    __syncthreads();

    if (EPI == 0) {         // split bf16: xi / z
        #pragma unroll 4
        for (int it = 0; it < 32; it++) {
            int idx = t + it*256, row = idx >> 6, c = idx & 63;
            float v = Cs[row][c];
            size_t m = bm + row;
            int gc = bn + c;
            if (gc < DI) Cb1[m*DI + gc]      = __float2bfloat16_rn(v);
            else         Cb2[m*DI + gc - DI] = __float2bfloat16_rn(v);
        }
    } else if (EPI == 1) {  // fp32, cols < NX, stride NXP
        #pragma unroll 4
        for (int it = 0; it < 32; it++) {
            int idx = t + it*256, row = idx >> 6, c = idx & 63;
            int gc = bn + c;
            if (gc < NX) Cf[(size_t)(bm + row) * NXP + gc] = Cs[row][c];
        }
    } else {                // transposed + residual
        int b  = bm >> 12;
        int l0 = bm & 4095;
        #pragma unroll 4
        for (int it = 0; it < 32; it++) {
            int n = 2*it + (t >> 7);
            int l = t & 127;
            size_t off = ((size_t)b * CC + bn + n) * LL + l0 + l;
            Cf[off] = Cs[l][n] + Xres[off];
        }
    }
}

// ---------------- K3: depthwise causal conv + bias + silu -> bf16 u ------
__global__ void k_conv(const float* __restrict__ cw, const float* __restrict__ cb) {
    int idx = blockIdx.x * blockDim.x + threadIdx.x;
    if (idx >= MM * DI) return;
    int d = idx % DI;
    int l = (idx / DI) % LL;
    int b = idx / (DI * LL);
    const __nv_bfloat16* xi = g_xi + ((size_t)b * LL) * DI + d;
    float acc = cb[d];
    #pragma unroll
    for (int j = 0; j < 4; j++) {
        int ll = l - 3 + j;
        if (ll >= 0)
            acc = fmaf(cw[d*4 + j], __bfloat162float(xi[(size_t)ll * DI]), acc);
    }
    float u = acc / (1.f + __expf(-acc));
    g_ub[idx] = __float2bfloat16_rn(u);
}

// ---------------- K4: dt = softplus(dt_r @ W_dt + b_dt) -> bf16 ----------
__global__ void __launch_bounds__(384)
k_dt(const float* __restrict__ Wdt, const float* __restrict__ bdt) {
    __shared__ float sdtr[64][DTR];
    int m0 = blockIdx.x * 64;
    int d  = threadIdx.x;
    for (int i = d; i < 64 * DTR; i += 384)
        sdtr[i / DTR][i % DTR] = g_xdbc[(size_t)(m0 + i / DTR) * NXP + (i % DTR)];
    float w[DTR];
    #pragma unroll
    for (int k = 0; k < DTR; k++) w[k] = Wdt[k*DI + d];
    float bd = bdt[d];
    __syncthreads();
    for (int r = 0; r < 64; r++) {
        float acc = bd;
        #pragma unroll
        for (int k = 0; k < DTR; k++) acc = fmaf(sdtr[r][k], w[k], acc);
        float dt = (acc > 20.f) ? acc : log1pf(__expf(acc));
        g_dt[(size_t)(m0 + r) * DI + d] = __float2bfloat16_rn(dt);
    }
}

// ---------------- K5a: scan pass1 — d-per-thread, packed states -----------
// grid (NC, BB), block 384 (= d). h[16] packed in 8 f32x2 regs.
__global__ void __launch_bounds__(384)
k_scan1(const float* __restrict__ Alog) {
    __shared__ float sB[CL][16];
    int c = blockIdx.x, b = blockIdx.y;
    int d = threadIdx.x;
    size_t m0 = (size_t)b * LL + (size_t)c * CL;
    for (int i = d; i < CL*16; i += 384) {
        int l = i >> 4, s = i & 15;
        sB[l][s] = g_xdbc[(m0 + l) * NXP + DTR + s];
    }
    float av[16];
    #pragma unroll
    for (int s = 0; s < 16; s++) av[s] = -__expf(Alog[d*DS + s]);
    float a1 = av[0];
    bool fast = true;
    #pragma unroll
    for (int s = 1; s < 16; s++) {
        float e = a1 * (float)(s+1);
        if (fabsf(av[s] - e) > 1e-4f * fmaxf(1.f, fabsf(e))) fast = false;
    }
    uint64_t h2[8];
    #pragma unroll
    for (int p = 0; p < 8; p++) h2[p] = pk(0.f, 0.f);
    float sumdt = 0.f;
    __syncthreads();
    const __nv_bfloat16* up  = g_ub + m0*DI + d;
    const __nv_bfloat16* dtp = g_dt + m0*DI + d;
    for (int l = 0; l < CL; l++) {
        float ut  = __bfloat162float(up [(size_t)l*DI]);
        float dtt = __bfloat162float(dtp[(size_t)l*DI]);
        float du  = dtt * ut;
        uint64_t du2 = pk(du, du);
        const uint64_t* B2 = (const uint64_t*)sB[l];
        if (fast) {
            float q = __expf(dtt * a1), q2 = q*q;
            uint64_t dA = pk(q, q2), st = pk(q2, q2);
            #pragma unroll
            for (int p = 0; p < 8; p++) {
                h2[p] = fma2(h2[p], dA, mul2(du2, B2[p]));
                if (p < 7) dA = mul2(dA, st);
            }
        } else {
            #pragma unroll
            for (int p = 0; p < 8; p++) {
                uint64_t dA = pk(__expf(dtt*av[2*p]), __expf(dtt*av[2*p+1]));
                h2[p] = fma2(h2[p], dA, mul2(du2, B2[p]));
            }
        }
        sumdt += dtt;
    }
    size_t base = ((size_t)(c*BB + b)*DI + d) * 16;
    float hv[16];
    #pragma unroll
    for (int p = 0; p < 8; p++) upk(h2[p], hv[2*p], hv[2*p+1]);
    #pragma unroll
    for (int p = 0; p < 4; p++)
        *(float4*)&g_hl[base + 4*p] =
            make_float4(hv[4*p], hv[4*p+1], hv[4*p+2], hv[4*p+3]);
    #pragma unroll
    for (int s = 0; s < 16; s += 4) {
        float4 pv;
        pv.x = __expf(av[s  ]*sumdt); pv.y = __expf(av[s+1]*sumdt);
        pv.z = __expf(av[s+2]*sumdt); pv.w = __expf(av[s+3]*sumdt);
        *(float4*)&g_P[base + s] = pv;
    }
}

// ---------------- K5b: serial combine over chunks -------------------------
// layout: [(c*BB + b)*DI + d]*16 + s ; chunk stride = BB*DI*16
__global__ void k_scan2() {
    int bds = blockIdx.x * blockDim.x + threadIdx.x;   // (b*DI+d)*16+s
    if (bds >= BB * DI * DS) return;
    const int STRIDE = BB * DI * DS;
    float h = 0.f;
    #pragma unroll
    for (int c = 0; c < NC; c++) {
        g_hin[(size_t)c * STRIDE + bds] = h;
        h = fmaf(g_P[(size_t)c * STRIDE + bds], h, g_hl[(size_t)c * STRIDE + bds]);
    }
}

// ---------------- K5c: scan pass3 — d-per-thread, emit gated y (bf16) -----
__global__ void __launch_bounds__(384)
k_scan3(const float* __restrict__ Alog, const float* __restrict__ Dp) {
    __shared__ float sB[CL][16];
    __shared__ float sC[CL][16];
    int c = blockIdx.x, b = blockIdx.y;
    int d = threadIdx.x;
    size_t m0 = (size_t)b * LL + (size_t)c * CL;
    for (int i = d; i < CL*16; i += 384) {
        int l = i >> 4, s = i & 15;
        sB[l][s] = g_xdbc[(m0 + l) * NXP + DTR + s];
        sC[l][s] = g_xdbc[(m0 + l) * NXP + DTR + DS + s];
    }
    float av[16];
    #pragma unroll
    for (int s = 0; s < 16; s++) av[s] = -__expf(Alog[d*DS + s]);
    float a1 = av[0];
    bool fast = true;
    #pragma unroll
    for (int s = 1; s < 16; s++) {
        float e = a1 * (float)(s+1);
        if (fabsf(av[s] - e) > 1e-4f * fmaxf(1.f, fabsf(e))) fast = false;
    }
    size_t base = ((size_t)(c*BB + b)*DI + d) * 16;
    uint64_t h2[8];
    #pragma unroll
    for (int p = 0; p < 4; p++) {
        float4 v = *(const float4*)&g_hin[base + 4*p];
        h2[2*p]   = pk(v.x, v.y);
        h2[2*p+1] = pk(v.z, v.w);
    }
    float Dpd = Dp[d];
    __syncthreads();
    const __nv_bfloat16* up  = g_ub + m0*DI + d;
    const __nv_bfloat16* dtp = g_dt + m0*DI + d;
    const __nv_bfloat16* zp  = g_z  + m0*DI + d;
    __nv_bfloat16*       yp  = g_yg + m0*DI + d;
    for (int l = 0; l < CL; l++) {
        float ut  = __bfloat162float(up [(size_t)l*DI]);
        float dtt = __bfloat162float(dtp[(size_t)l*DI]);
        float du  = dtt * ut;
        uint64_t du2 = pk(du, du);
        const uint64_t* B2 = (const uint64_t*)sB[l];
        const uint64_t* C2 = (const uint64_t*)sC[l];
        uint64_t acc = pk(0.f, 0.f);
        if (fast) {
            float q = __expf(dtt * a1), q2 = q*q;
            uint64_t dA = pk(q, q2), st = pk(q2, q2);
            #pragma unroll
            for (int p = 0; p < 8; p++) {
                h2[p] = fma2(h2[p], dA, mul2(du2, B2[p]));
                acc   = fma2(h2[p], C2[p], acc);
                if (p < 7) dA = mul2(dA, st);
            }
        } else {
            #pragma unroll
            for (int p = 0; p < 8; p++) {
                uint64_t dA = pk(__expf(dtt*av[2*p]), __expf(dtt*av[2*p+1]));
                h2[p] = fma2(h2[p], dA, mul2(du2, B2[p]));
                acc   = fma2(h2[p], C2[p], acc);
            }
        }
        float alo, ahi; upk(acc, alo, ahi);
        float y = alo + ahi + ut * Dpd;
        float z = __bfloat162float(zp[(size_t)l*DI]);
        y *= z / (1.f + __expf(-z));
        yp[(size_t)l*DI] = __float2bfloat16_rn(y);
    }
}

// ---------------- launch ----------------
extern "C" void kernel_launch(void* const* d_in, const int* in_sizes, int n_in,
                              void* d_out, int out_size) {
    const float* x      = (const float*)d_in[0];
    const float* ln_g   = (const float*)d_in[1];
    const float* ln_b   = (const float*)d_in[2];
    const float* W_in   = (const float*)d_in[3];
    const float* conv_w = (const float*)d_in[4];
    const float* conv_b = (const float*)d_in[5];
    const float* W_x    = (const float*)d_in[6];
    const float* W_dt   = (const float*)d_in[7];
    const float* b_dt   = (const float*)d_in[8];
    const float* A_log  = (const float*)d_in[9];
    const float* Dp     = (const float*)d_in[10];
    const float* W_out  = (const float*)d_in[11];
    float* out = (float*)d_out;

    __nv_bfloat16 *p_xn, *p_xi, *p_z, *p_ub, *p_yg;
    float *p_xdbc;
    cudaGetSymbolAddress((void**)&p_xn,   g_xn);
    cudaGetSymbolAddress((void**)&p_xi,   g_xi);
    cudaGetSymbolAddress((void**)&p_z,    g_z);
    cudaGetSymbolAddress((void**)&p_ub,   g_ub);
    cudaGetSymbolAddress((void**)&p_xdbc, g_xdbc);
    cudaGetSymbolAddress((void**)&p_yg,   g_yg);

    {   // layernorm -> bf16 (B,L,C)
        dim3 grid(LL/32, BB), blk(32, 8);
        k_ln<<<grid, blk>>>(x, ln_g, ln_b);
    }
    {   // GEMM1: [xi|z] = xn @ W_in, split bf16 epilogue
        dim3 grid((2*DI)/64, MM/128);
        k_bgemm16<CC, false, 0><<<grid, 256>>>(p_xn, W_in, 2*DI,
                                               nullptr, p_xi, p_z, nullptr);
    }
    {   // conv + silu -> ub (bf16)
        int n = MM * DI;
        k_conv<<<(n + 255)/256, 256>>>(conv_w, conv_b);
    }
    {   // xdbc = u @ W_x (44 valid cols, fp32 out stride 64)
        dim3 grid(1, MM/128);
        k_bgemm16<DI, true, 1><<<grid, 256>>>(p_ub, W_x, NX,
                                              p_xdbc, nullptr, nullptr, nullptr);
    }
    // dt (bf16)
    k_dt<<<MM/64, 384>>>(W_dt, b_dt);
    // chunked scan (d-per-thread, packed)
    {
        dim3 grid(NC, BB);
        k_scan1<<<grid, 384>>>(A_log);
        k_scan2<<<(BB*DI*DS + 255)/256, 256>>>();
        k_scan3<<<grid, 384>>>(A_log, Dp);
    }
    {   // GEMM3 fused transpose+residual: out = (yg @ W_out)^T + x
        dim3 grid(CC/64, MM/128);
        k_bgemm16<DI, false, 2><<<grid, 256>>>(p_yg, W_out, CC,
                                               out, nullptr, nullptr, x);
    }
}